// round 3
// baseline (speedup 1.0000x reference)
#include <cuda_runtime.h>
#include <cstdint>

#define N_NODES  50000
#define N_HEDGES 5000
#define NNZ      800000
#define IN_C     128
#define D1       256
#define D2       64

// ---------------- scratch (static device memory; no allocation) ----------------
__device__ int   g_deg[N_NODES];
__device__ int   g_cnt[N_HEDGES];
__device__ int   g_nptr[N_NODES + 1];
__device__ int   g_hptr[N_HEDGES + 1];
__device__ int   g_bsumN[128];
__device__ int   g_bsumH[16];
__device__ int   g_node_hedges[NNZ];   // per-node list of hyperedge ids
__device__ int   g_hedge_nodes[NNZ];   // per-hyperedge list of node ids
__device__ float g_dinv[N_NODES];
__device__ float g_binv[N_HEDGES];
__device__ float g_e1[(size_t)N_HEDGES * IN_C];
__device__ float g_y1[(size_t)N_NODES * IN_C];
__device__ float g_h [(size_t)N_NODES * D1];
__device__ float g_hw[(size_t)N_NODES * D2];
__device__ float g_e2[(size_t)N_HEDGES * D2];

// ---------------- CSR build ----------------
__global__ void k_zero_counts() {
    int i = blockIdx.x * blockDim.x + threadIdx.x;
    if (i < N_NODES)  g_deg[i] = 0;
    if (i < N_HEDGES) g_cnt[i] = 0;
}

__global__ void k_count(const int* __restrict__ nidx, const int* __restrict__ hidx) {
    int i = blockIdx.x * blockDim.x + threadIdx.x;
    if (i >= NNZ) return;
    atomicAdd(&g_deg[nidx[i]], 1);
    atomicAdd(&g_cnt[hidx[i]], 1);
}

// sel: 0 = node arrays, 1 = hedge arrays
__global__ void k_block_sum(int sel) {
    const int* in = sel ? g_cnt : g_deg;
    int n         = sel ? N_HEDGES : N_NODES;
    int* bs       = sel ? g_bsumH : g_bsumN;
    __shared__ int s[512];
    int b = blockIdx.x, t = threadIdx.x, i = b * 512 + t;
    s[t] = (i < n) ? in[i] : 0;
    __syncthreads();
    for (int off = 256; off > 0; off >>= 1) {
        if (t < off) s[t] += s[t + off];
        __syncthreads();
    }
    if (t == 0) bs[b] = s[0];
}

__global__ void k_scan_small(int sel) {  // in-place exclusive scan of block sums
    int* data = sel ? g_bsumH : g_bsumN;
    int n     = sel ? ((N_HEDGES + 511) / 512) : ((N_NODES + 511) / 512);
    __shared__ int s[1024];
    int t = threadIdx.x;
    int v = (t < n) ? data[t] : 0;
    s[t] = v;
    __syncthreads();
    for (int off = 1; off < 1024; off <<= 1) {
        int x = (t >= off) ? s[t - off] : 0;
        __syncthreads();
        s[t] += x;
        __syncthreads();
    }
    if (t < n) data[t] = s[t] - v;  // exclusive
}

__global__ void k_scan_final(int sel) {
    const int* in   = sel ? g_cnt : g_deg;
    const int* boff = sel ? g_bsumH : g_bsumN;
    int* ptr        = sel ? g_hptr : g_nptr;
    int n           = sel ? N_HEDGES : N_NODES;
    __shared__ int s[512];
    int b = blockIdx.x, t = threadIdx.x, i = b * 512 + t;
    int v = (i < n) ? in[i] : 0;
    s[t] = v;
    __syncthreads();
    for (int off = 1; off < 512; off <<= 1) {
        int x = (t >= off) ? s[t - off] : 0;
        __syncthreads();
        s[t] += x;
        __syncthreads();
    }
    int excl = s[t] - v + boff[b];
    if (i < n) ptr[i] = excl;
    if (i == n - 1) ptr[n] = excl + v;
}

__global__ void k_fill(const int* __restrict__ nidx, const int* __restrict__ hidx) {
    int i = blockIdx.x * blockDim.x + threadIdx.x;
    if (i >= NNZ) return;
    int n = nidx[i], e = hidx[i];
    int p = atomicAdd(&g_deg[n], 1);
    g_node_hedges[g_nptr[n] + p] = e;
    int q = atomicAdd(&g_cnt[e], 1);
    g_hedge_nodes[g_hptr[e] + q] = n;
}

__global__ void k_inv() {
    int i = blockIdx.x * blockDim.x + threadIdx.x;
    if (i < N_NODES) {
        int d = g_nptr[i + 1] - g_nptr[i];
        g_dinv[i] = d ? 1.0f / (float)d : 0.0f;
    }
    if (i < N_HEDGES) {
        int c = g_hptr[i + 1] - g_hptr[i];
        g_binv[i] = c ? 1.0f / (float)c : 0.0f;
    }
}

// ---------------- aggregation (CSR, no atomics) ----------------
// hyperedge e: e1[e,:] = Binv[e] * sum_{n in e} x[n,:]   (128 dims, warp per hedge)
__global__ void k_hedge_agg128(const float* __restrict__ x) {
    int w = (blockIdx.x * blockDim.x + threadIdx.x) >> 5;
    if (w >= N_HEDGES) return;
    int lane = threadIdx.x & 31;
    int beg = g_hptr[w], end = g_hptr[w + 1];
    float4 acc = make_float4(0.f, 0.f, 0.f, 0.f);
    for (int j = beg; j < end; j++) {
        int n = g_hedge_nodes[j];
        float4 v = *(const float4*)(x + (size_t)n * IN_C + lane * 4);
        acc.x += v.x; acc.y += v.y; acc.z += v.z; acc.w += v.w;
    }
    float s = g_binv[w];
    acc.x *= s; acc.y *= s; acc.z *= s; acc.w *= s;
    *(float4*)(g_e1 + (size_t)w * IN_C + lane * 4) = acc;
}

// node n: y1[n,:] = sum_{e of n} e1[e,:]   (Dinv folded into GEMM1 A-read)
__global__ void k_node_agg128() {
    int w = (blockIdx.x * blockDim.x + threadIdx.x) >> 5;
    if (w >= N_NODES) return;
    int lane = threadIdx.x & 31;
    int beg = g_nptr[w], end = g_nptr[w + 1];
    float4 acc = make_float4(0.f, 0.f, 0.f, 0.f);
    for (int j = beg; j < end; j++) {
        int e = g_node_hedges[j];
        float4 v = *(const float4*)(g_e1 + (size_t)e * IN_C + lane * 4);
        acc.x += v.x; acc.y += v.y; acc.z += v.z; acc.w += v.w;
    }
    *(float4*)(g_y1 + (size_t)w * IN_C + lane * 4) = acc;
}

// hyperedge e: e2[e,:] = Binv[e] * sum_{n in e} hw[n,:]  (64 dims, float2 per lane)
__global__ void k_hedge_agg64() {
    int w = (blockIdx.x * blockDim.x + threadIdx.x) >> 5;
    if (w >= N_HEDGES) return;
    int lane = threadIdx.x & 31;
    int beg = g_hptr[w], end = g_hptr[w + 1];
    float2 acc = make_float2(0.f, 0.f);
    for (int j = beg; j < end; j++) {
        int n = g_hedge_nodes[j];
        float2 v = *(const float2*)(g_hw + (size_t)n * D2 + lane * 2);
        acc.x += v.x; acc.y += v.y;
    }
    float s = g_binv[w];
    acc.x *= s; acc.y *= s;
    *(float2*)(g_e2 + (size_t)w * D2 + lane * 2) = acc;
}

// node n: out[n,:] = relu(Dinv[n] * sum_{e of n} e2[e,:] + b2)  (fused epilogue)
__global__ void k_node_agg64_out(const float* __restrict__ b2, float* __restrict__ out) {
    int w = (blockIdx.x * blockDim.x + threadIdx.x) >> 5;
    if (w >= N_NODES) return;
    int lane = threadIdx.x & 31;
    int beg = g_nptr[w], end = g_nptr[w + 1];
    float2 acc = make_float2(0.f, 0.f);
    for (int j = beg; j < end; j++) {
        int e = g_node_hedges[j];
        float2 v = *(const float2*)(g_e2 + (size_t)e * D2 + lane * 2);
        acc.x += v.x; acc.y += v.y;
    }
    float di = g_dinv[w];
    float2 bb = *(const float2*)(b2 + lane * 2);
    float o0 = fmaxf(acc.x * di + bb.x, 0.f);
    float o1 = fmaxf(acc.y * di + bb.y, 0.f);
    *(float2*)(out + (size_t)w * D2 + lane * 2) = make_float2(o0, o1);
}

// ---------------- tiled fp32 GEMM: C[M,N] = op(A[M,K]) @ B[K,N] ----------------
// optional per-row scale on A, optional bias + relu epilogue
__device__ __forceinline__ void gemm_body(
    const float* __restrict__ A, const float* __restrict__ rowScale,
    const float* __restrict__ B, const float* __restrict__ bias,
    float* __restrict__ C, int M, int N, int K, bool doRelu)
{
    constexpr int BM = 64, BN = 64, BK = 16;
    __shared__ float As[BK][BM + 4];   // transposed tile, row stride 272B (16B-aligned)
    __shared__ float Bs[BK][BN];
    int bm = blockIdx.y * BM, bn = blockIdx.x * BN;
    int tid = threadIdx.x;                 // 256 threads
    int tr = (tid >> 4) << 2;              // 4-row micro-tile
    int tc = (tid & 15) << 2;              // 4-col micro-tile
    float acc[4][4] = {};
    for (int k0 = 0; k0 < K; k0 += BK) {
        #pragma unroll
        for (int i = 0; i < 4; i++) {      // load 64x16 A tile, transposed
            int idx = tid + i * 256;
            int m = idx >> 4, kk = idx & 15;
            int gm = bm + m;
            float v = 0.f;
            if (gm < M) {
                v = A[(size_t)gm * K + k0 + kk];
                if (rowScale) v *= rowScale[gm];
            }
            As[kk][m] = v;
        }
        #pragma unroll
        for (int i = 0; i < 4; i++) {      // load 16x64 B tile
            int idx = tid + i * 256;
            int kk = idx >> 6, n = idx & 63;
            Bs[kk][n] = B[(size_t)(k0 + kk) * N + bn + n];
        }
        __syncthreads();
        #pragma unroll
        for (int kk = 0; kk < BK; kk++) {
            float4 a = *(const float4*)&As[kk][tr];
            float4 b = *(const float4*)&Bs[kk][tc];
            acc[0][0] += a.x * b.x; acc[0][1] += a.x * b.y; acc[0][2] += a.x * b.z; acc[0][3] += a.x * b.w;
            acc[1][0] += a.y * b.x; acc[1][1] += a.y * b.y; acc[1][2] += a.y * b.z; acc[1][3] += a.y * b.w;
            acc[2][0] += a.z * b.x; acc[2][1] += a.z * b.y; acc[2][2] += a.z * b.z; acc[2][3] += a.z * b.w;
            acc[3][0] += a.w * b.x; acc[3][1] += a.w * b.y; acc[3][2] += a.w * b.z; acc[3][3] += a.w * b.w;
        }
        __syncthreads();
    }
    #pragma unroll
    for (int i = 0; i < 4; i++) {
        int gm = bm + tr + i;
        if (gm >= M) continue;
        #pragma unroll
        for (int j = 0; j < 4; j++) {
            int gn = bn + tc + j;
            float v = acc[i][j];
            if (bias) v += bias[gn];
            if (doRelu) v = fmaxf(v, 0.f);
            C[(size_t)gm * N + gn] = v;
        }
    }
}

// h = relu( (Dinv .* y1) @ W1 + b1 )
__global__ void k_gemm1(const float* __restrict__ W1, const float* __restrict__ b1) {
    gemm_body(g_y1, g_dinv, W1, b1, g_h, N_NODES, D1, IN_C, true);
}
// hw = h @ W2
__global__ void k_gemm2(const float* __restrict__ W2) {
    gemm_body(g_h, nullptr, W2, nullptr, g_hw, N_NODES, D2, D1, false);
}

// ---------------- launch ----------------
extern "C" void kernel_launch(void* const* d_in, const int* in_sizes, int n_in,
                              void* d_out, int out_size) {
    const float* x  = (const float*)d_in[0];
    const int* edge = (const int*)d_in[1];
    const float* W1 = (const float*)d_in[2];
    const float* b1 = (const float*)d_in[3];
    const float* W2 = (const float*)d_in[4];
    const float* b2 = (const float*)d_in[5];
    float* out = (float*)d_out;
    const int* nidx = edge;
    const int* hidx = edge + NNZ;

    const int NB_N = (N_NODES + 511) / 512;   // 98
    const int NB_H = (N_HEDGES + 511) / 512;  // 10

    // CSR build
    k_zero_counts<<<(N_NODES + 255) / 256, 256>>>();
    k_count<<<(NNZ + 255) / 256, 256>>>(nidx, hidx);
    k_block_sum<<<NB_N, 512>>>(0);
    k_block_sum<<<NB_H, 512>>>(1);
    k_scan_small<<<1, 1024>>>(0);
    k_scan_small<<<1, 1024>>>(1);
    k_scan_final<<<NB_N, 512>>>(0);
    k_scan_final<<<NB_H, 512>>>(1);
    k_zero_counts<<<(N_NODES + 255) / 256, 256>>>();
    k_fill<<<(NNZ + 255) / 256, 256>>>(nidx, hidx);
    k_inv<<<(N_NODES + 255) / 256, 256>>>();

    // Layer 1: aggregate at 128 dims (Agg(X)@W1 == Agg(X@W1)), then GEMM+bias+relu
    k_hedge_agg128<<<(N_HEDGES * 32 + 255) / 256, 256>>>(x);
    k_node_agg128<<<(N_NODES * 32 + 255) / 256, 256>>>();
    {
        dim3 grid(D1 / 64, (N_NODES + 63) / 64);
        k_gemm1<<<grid, 256>>>(W1, b1);
    }

    // Layer 2: GEMM first (aggregate at 64 dims), fused Dinv+b2+relu epilogue
    {
        dim3 grid(D2 / 64, (N_NODES + 63) / 64);
        k_gemm2<<<grid, 256>>>(W2);
    }
    k_hedge_agg64<<<(N_HEDGES * 32 + 255) / 256, 256>>>();
    k_node_agg64_out<<<(N_NODES * 32 + 255) / 256, 256>>>(b2, out);
}

// round 5
// speedup vs baseline: 1.1888x; 1.1888x over previous
#include <cuda_runtime.h>
#include <cstdint>

#define N_NODES  50000
#define N_HEDGES 5000
#define NNZ      800000
#define IN_C     128
#define D1       256
#define D2       64

// ---------------- scratch (static device memory; no allocation) ----------------
__device__ int   g_deg[N_NODES];
__device__ int   g_cnt[N_HEDGES];
__device__ int   g_nptr[N_NODES + 1];
__device__ int   g_hptr[N_HEDGES + 1];
__device__ int   g_bsumN[128];
__device__ int   g_bsumH[16];
__device__ int   g_node_hedges[NNZ];   // per-node list of hyperedge ids
__device__ int   g_hedge_nodes[NNZ];   // per-hyperedge list of node ids
__device__ float g_dinv[N_NODES];
__device__ float g_binv[N_HEDGES];
__device__ float g_e1 [(size_t)N_HEDGES * IN_C];   // Binv * H^T x
__device__ float g_ew1[(size_t)N_HEDGES * D1];     // e1 @ W1
__device__ float g_h  [(size_t)N_NODES * D1];      // relu(Dinv*H*ew1 + b1)
__device__ float g_hw [(size_t)N_NODES * D2];      // h @ W2
__device__ float g_e2 [(size_t)N_HEDGES * D2];

// ---------------- CSR build ----------------
__global__ void k_zero_counts() {
    int i = blockIdx.x * blockDim.x + threadIdx.x;
    if (i < N_NODES)  g_deg[i] = 0;
    if (i < N_HEDGES) g_cnt[i] = 0;
}

__global__ void k_count(const int* __restrict__ nidx, const int* __restrict__ hidx) {
    int i = blockIdx.x * blockDim.x + threadIdx.x;
    if (i >= NNZ) return;
    atomicAdd(&g_deg[nidx[i]], 1);
    atomicAdd(&g_cnt[hidx[i]], 1);
}

// sel: 0 = node arrays, 1 = hedge arrays
__global__ void k_block_sum(int sel) {
    const int* in = sel ? g_cnt : g_deg;
    int n         = sel ? N_HEDGES : N_NODES;
    int* bs       = sel ? g_bsumH : g_bsumN;
    __shared__ int s[512];
    int b = blockIdx.x, t = threadIdx.x, i = b * 512 + t;
    s[t] = (i < n) ? in[i] : 0;
    __syncthreads();
    for (int off = 256; off > 0; off >>= 1) {
        if (t < off) s[t] += s[t + off];
        __syncthreads();
    }
    if (t == 0) bs[b] = s[0];
}

__global__ void k_scan_small(int sel) {  // in-place exclusive scan of block sums
    int* data = sel ? g_bsumH : g_bsumN;
    int n     = sel ? ((N_HEDGES + 511) / 512) : ((N_NODES + 511) / 512);
    __shared__ int s[1024];
    int t = threadIdx.x;
    int v = (t < n) ? data[t] : 0;
    s[t] = v;
    __syncthreads();
    for (int off = 1; off < 1024; off <<= 1) {
        int x = (t >= off) ? s[t - off] : 0;
        __syncthreads();
        s[t] += x;
        __syncthreads();
    }
    if (t < n) data[t] = s[t] - v;  // exclusive
}

__global__ void k_scan_final(int sel) {
    const int* in   = sel ? g_cnt : g_deg;
    const int* boff = sel ? g_bsumH : g_bsumN;
    int* ptr        = sel ? g_hptr : g_nptr;
    int n           = sel ? N_HEDGES : N_NODES;
    __shared__ int s[512];
    int b = blockIdx.x, t = threadIdx.x, i = b * 512 + t;
    int v = (i < n) ? in[i] : 0;
    s[t] = v;
    __syncthreads();
    for (int off = 1; off < 512; off <<= 1) {
        int x = (t >= off) ? s[t - off] : 0;
        __syncthreads();
        s[t] += x;
        __syncthreads();
    }
    int excl = s[t] - v + boff[b];
    if (i < n) ptr[i] = excl;
    if (i == n - 1) ptr[n] = excl + v;
}

__global__ void k_fill(const int* __restrict__ nidx, const int* __restrict__ hidx) {
    int i = blockIdx.x * blockDim.x + threadIdx.x;
    if (i >= NNZ) return;
    int n = nidx[i], e = hidx[i];
    int p = atomicAdd(&g_deg[n], 1);
    g_node_hedges[g_nptr[n] + p] = e;
    int q = atomicAdd(&g_cnt[e], 1);
    g_hedge_nodes[g_hptr[e] + q] = n;
}

__global__ void k_inv() {
    int i = blockIdx.x * blockDim.x + threadIdx.x;
    if (i < N_NODES) {
        int d = g_nptr[i + 1] - g_nptr[i];
        g_dinv[i] = d ? 1.0f / (float)d : 0.0f;
    }
    if (i < N_HEDGES) {
        int c = g_hptr[i + 1] - g_hptr[i];
        g_binv[i] = c ? 1.0f / (float)c : 0.0f;
    }
}

// ---------------- aggregation (CSR, no atomics) ----------------
// hyperedge e: e1[e,:] = Binv[e] * sum_{n in e} x[n,:]   (128 dims, warp per hedge)
__global__ void k_hedge_agg128(const float* __restrict__ x) {
    int w = (blockIdx.x * blockDim.x + threadIdx.x) >> 5;
    if (w >= N_HEDGES) return;
    int lane = threadIdx.x & 31;
    int beg = g_hptr[w], end = g_hptr[w + 1];
    float4 accA = make_float4(0.f, 0.f, 0.f, 0.f);
    float4 accB = make_float4(0.f, 0.f, 0.f, 0.f);
    int j = beg;
    for (; j + 1 < end; j += 2) {   // 2-way unroll for MLP
        int n0 = g_hedge_nodes[j];
        int n1 = g_hedge_nodes[j + 1];
        float4 v0 = *(const float4*)(x + (size_t)n0 * IN_C + lane * 4);
        float4 v1 = *(const float4*)(x + (size_t)n1 * IN_C + lane * 4);
        accA.x += v0.x; accA.y += v0.y; accA.z += v0.z; accA.w += v0.w;
        accB.x += v1.x; accB.y += v1.y; accB.z += v1.z; accB.w += v1.w;
    }
    if (j < end) {
        int n0 = g_hedge_nodes[j];
        float4 v0 = *(const float4*)(x + (size_t)n0 * IN_C + lane * 4);
        accA.x += v0.x; accA.y += v0.y; accA.z += v0.z; accA.w += v0.w;
    }
    float s = g_binv[w];
    float4 o;
    o.x = (accA.x + accB.x) * s; o.y = (accA.y + accB.y) * s;
    o.z = (accA.z + accB.z) * s; o.w = (accA.w + accB.w) * s;
    *(float4*)(g_e1 + (size_t)w * IN_C + lane * 4) = o;
}

// node n: h[n,:] = relu( Dinv[n] * sum_{e of n} ew1[e,:] + b1 )  (256 dims)
__global__ void k_node_agg256(const float* __restrict__ b1) {
    int w = (blockIdx.x * blockDim.x + threadIdx.x) >> 5;
    if (w >= N_NODES) return;
    int lane = threadIdx.x & 31;
    int beg = g_nptr[w], end = g_nptr[w + 1];
    float4 a0 = make_float4(0.f, 0.f, 0.f, 0.f);  // cols [4*lane, 4*lane+4)
    float4 a1 = make_float4(0.f, 0.f, 0.f, 0.f);  // cols [128+4*lane, ...)
    int j = beg;
    for (; j + 1 < end; j += 2) {   // 2 edges in flight -> 4 independent loads
        int e0 = g_node_hedges[j];
        int e1 = g_node_hedges[j + 1];
        const float4* p0 = (const float4*)(g_ew1 + (size_t)e0 * D1) + lane;
        const float4* p1 = (const float4*)(g_ew1 + (size_t)e1 * D1) + lane;
        float4 v00 = p0[0], v01 = p0[32];
        float4 v10 = p1[0], v11 = p1[32];
        a0.x += v00.x + v10.x; a0.y += v00.y + v10.y; a0.z += v00.z + v10.z; a0.w += v00.w + v10.w;
        a1.x += v01.x + v11.x; a1.y += v01.y + v11.y; a1.z += v01.z + v11.z; a1.w += v01.w + v11.w;
    }
    if (j < end) {
        int e0 = g_node_hedges[j];
        const float4* p0 = (const float4*)(g_ew1 + (size_t)e0 * D1) + lane;
        float4 v00 = p0[0], v01 = p0[32];
        a0.x += v00.x; a0.y += v00.y; a0.z += v00.z; a0.w += v00.w;
        a1.x += v01.x; a1.y += v01.y; a1.z += v01.z; a1.w += v01.w;
    }
    float di = g_dinv[w];
    float4 bA = *(const float4*)(b1 + lane * 4);
    float4 bB = *(const float4*)(b1 + 128 + lane * 4);
    float4 o0, o1;
    o0.x = fmaxf(a0.x * di + bA.x, 0.f); o0.y = fmaxf(a0.y * di + bA.y, 0.f);
    o0.z = fmaxf(a0.z * di + bA.z, 0.f); o0.w = fmaxf(a0.w * di + bA.w, 0.f);
    o1.x = fmaxf(a1.x * di + bB.x, 0.f); o1.y = fmaxf(a1.y * di + bB.y, 0.f);
    o1.z = fmaxf(a1.z * di + bB.z, 0.f); o1.w = fmaxf(a1.w * di + bB.w, 0.f);
    float4* outp = (float4*)(g_h + (size_t)w * D1) + lane;
    outp[0] = o0;
    outp[32] = o1;
}

// hyperedge e: e2[e,:] = Binv[e] * sum_{n in e} hw[n,:]  (64 dims, float2 per lane)
__global__ void k_hedge_agg64() {
    int w = (blockIdx.x * blockDim.x + threadIdx.x) >> 5;
    if (w >= N_HEDGES) return;
    int lane = threadIdx.x & 31;
    int beg = g_hptr[w], end = g_hptr[w + 1];
    float2 aA = make_float2(0.f, 0.f);
    float2 aB = make_float2(0.f, 0.f);
    int j = beg;
    for (; j + 1 < end; j += 2) {
        int n0 = g_hedge_nodes[j];
        int n1 = g_hedge_nodes[j + 1];
        float2 v0 = *(const float2*)(g_hw + (size_t)n0 * D2 + lane * 2);
        float2 v1 = *(const float2*)(g_hw + (size_t)n1 * D2 + lane * 2);
        aA.x += v0.x; aA.y += v0.y;
        aB.x += v1.x; aB.y += v1.y;
    }
    if (j < end) {
        int n0 = g_hedge_nodes[j];
        float2 v0 = *(const float2*)(g_hw + (size_t)n0 * D2 + lane * 2);
        aA.x += v0.x; aA.y += v0.y;
    }
    float s = g_binv[w];
    float2 o = make_float2((aA.x + aB.x) * s, (aA.y + aB.y) * s);
    *(float2*)(g_e2 + (size_t)w * D2 + lane * 2) = o;
}

// node n: out[n,:] = relu(Dinv[n] * sum_{e of n} e2[e,:] + b2)  (fused epilogue)
__global__ void k_node_agg64_out(const float* __restrict__ b2, float* __restrict__ out) {
    int w = (blockIdx.x * blockDim.x + threadIdx.x) >> 5;
    if (w >= N_NODES) return;
    int lane = threadIdx.x & 31;
    int beg = g_nptr[w], end = g_nptr[w + 1];
    float2 aA = make_float2(0.f, 0.f);
    float2 aB = make_float2(0.f, 0.f);
    int j = beg;
    for (; j + 1 < end; j += 2) {
        int e0 = g_node_hedges[j];
        int e1 = g_node_hedges[j + 1];
        float2 v0 = *(const float2*)(g_e2 + (size_t)e0 * D2 + lane * 2);
        float2 v1 = *(const float2*)(g_e2 + (size_t)e1 * D2 + lane * 2);
        aA.x += v0.x; aA.y += v0.y;
        aB.x += v1.x; aB.y += v1.y;
    }
    if (j < end) {
        int e0 = g_node_hedges[j];
        float2 v0 = *(const float2*)(g_e2 + (size_t)e0 * D2 + lane * 2);
        aA.x += v0.x; aA.y += v0.y;
    }
    float di = g_dinv[w];
    float2 bb = *(const float2*)(b2 + lane * 2);
    float o0 = fmaxf((aA.x + aB.x) * di + bb.x, 0.f);
    float o1 = fmaxf((aA.y + aB.y) * di + bb.y, 0.f);
    *(float2*)(out + (size_t)w * D2 + lane * 2) = make_float2(o0, o1);
}

// ---------------- tiled fp32 GEMM: C[M,N] = A[M,K] @ B[K,N] ----------------
__device__ __forceinline__ void gemm_body(
    const float* __restrict__ A,
    const float* __restrict__ B, const float* __restrict__ bias,
    float* __restrict__ C, int M, int N, int K, bool doRelu)
{
    constexpr int BM = 64, BN = 64, BK = 16;
    __shared__ float As[BK][BM + 4];
    __shared__ float Bs[BK][BN];
    int bm = blockIdx.y * BM, bn = blockIdx.x * BN;
    int tid = threadIdx.x;                 // 256 threads
    int tr = (tid >> 4) << 2;              // 4-row micro-tile
    int tc = (tid & 15) << 2;              // 4-col micro-tile
    float acc[4][4] = {};
    for (int k0 = 0; k0 < K; k0 += BK) {
        #pragma unroll
        for (int i = 0; i < 4; i++) {      // load 64x16 A tile, transposed
            int idx = tid + i * 256;
            int m = idx >> 4, kk = idx & 15;
            int gm = bm + m;
            As[kk][m] = (gm < M) ? A[(size_t)gm * K + k0 + kk] : 0.f;
        }
        #pragma unroll
        for (int i = 0; i < 4; i++) {      // load 16x64 B tile
            int idx = tid + i * 256;
            int kk = idx >> 6, n = idx & 63;
            Bs[kk][n] = B[(size_t)(k0 + kk) * N + bn + n];
        }
        __syncthreads();
        #pragma unroll
        for (int kk = 0; kk < BK; kk++) {
            float4 a = *(const float4*)&As[kk][tr];
            float4 b = *(const float4*)&Bs[kk][tc];
            acc[0][0] += a.x * b.x; acc[0][1] += a.x * b.y; acc[0][2] += a.x * b.z; acc[0][3] += a.x * b.w;
            acc[1][0] += a.y * b.x; acc[1][1] += a.y * b.y; acc[1][2] += a.y * b.z; acc[1][3] += a.y * b.w;
            acc[2][0] += a.z * b.x; acc[2][1] += a.z * b.y; acc[2][2] += a.z * b.z; acc[2][3] += a.z * b.w;
            acc[3][0] += a.w * b.x; acc[3][1] += a.w * b.y; acc[3][2] += a.w * b.z; acc[3][3] += a.w * b.w;
        }
        __syncthreads();
    }
    #pragma unroll
    for (int i = 0; i < 4; i++) {
        int gm = bm + tr + i;
        if (gm >= M) continue;
        #pragma unroll
        for (int j = 0; j < 4; j++) {
            int gn = bn + tc + j;
            float v = acc[i][j];
            if (bias) v += bias[gn];
            if (doRelu) v = fmaxf(v, 0.f);
            C[(size_t)gm * N + gn] = v;
        }
    }
}

// ew1 = e1 @ W1   (5000 x 256, tiny hedge-side GEMM; bias folded into node agg)
__global__ void k_gemm_e1(const float* __restrict__ W1) {
    gemm_body(g_e1, W1, nullptr, g_ew1, N_HEDGES, D1, IN_C, false);
}
// hw = h @ W2
__global__ void k_gemm2(const float* __restrict__ W2) {
    gemm_body(g_h, W2, nullptr, g_hw, N_NODES, D2, D1, false);
}

// ---------------- launch ----------------
extern "C" void kernel_launch(void* const* d_in, const int* in_sizes, int n_in,
                              void* d_out, int out_size) {
    const float* x  = (const float*)d_in[0];
    const int* edge = (const int*)d_in[1];
    const float* W1 = (const float*)d_in[2];
    const float* b1 = (const float*)d_in[3];
    const float* W2 = (const float*)d_in[4];
    const float* b2 = (const float*)d_in[5];
    float* out = (float*)d_out;
    const int* nidx = edge;
    const int* hidx = edge + NNZ;

    const int NB_N = (N_NODES + 511) / 512;   // 98
    const int NB_H = (N_HEDGES + 511) / 512;  // 10

    // CSR build
    k_zero_counts<<<(N_NODES + 255) / 256, 256>>>();
    k_count<<<(NNZ + 255) / 256, 256>>>(nidx, hidx);
    k_block_sum<<<NB_N, 512>>>(0);
    k_block_sum<<<NB_H, 512>>>(1);
    k_scan_small<<<1, 1024>>>(0);
    k_scan_small<<<1, 1024>>>(1);
    k_scan_final<<<NB_N, 512>>>(0);
    k_scan_final<<<NB_H, 512>>>(1);
    k_zero_counts<<<(N_NODES + 255) / 256, 256>>>();
    k_fill<<<(NNZ + 255) / 256, 256>>>(nidx, hidx);
    k_inv<<<(N_NODES + 255) / 256, 256>>>();

    // Layer 1: hedge agg @128 -> tiny hedge-side GEMM -> node agg @256 (+bias+relu)
    k_hedge_agg128<<<(N_HEDGES * 32 + 255) / 256, 256>>>(x);
    {
        dim3 grid(D1 / 64, (N_HEDGES + 63) / 64);
        k_gemm_e1<<<grid, 256>>>(W1);
    }
    k_node_agg256<<<(N_NODES * 32 + 255) / 256, 256>>>(b1);

    // Layer 2: GEMM first (aggregate at 64 dims), fused Dinv+b2+relu epilogue
    {
        dim3 grid(D2 / 64, (N_NODES + 63) / 64);
        k_gemm2<<<grid, 256>>>(W2);
    }
    k_hedge_agg64<<<(N_HEDGES * 32 + 255) / 256, 256>>>();
    k_node_agg64_out<<<(N_NODES * 32 + 255) / 256, 256>>>(b2, out);
}

// round 7
// speedup vs baseline: 1.2534x; 1.0543x over previous
#include <cuda_runtime.h>
#include <cstdint>

#define N_NODES  50000
#define N_HEDGES 5000
#define NNZ      800000
#define IN_C     128
#define D1       256
#define D2       64

#define NB_N 98   // ceil(50000/512)
#define NB_H 10   // ceil(5000/512)

// ---------------- scratch (static device memory; no allocation) ----------------
__device__ int   g_deg [N_NODES];     // count pass
__device__ int   g_cnt [N_HEDGES];
__device__ int   g_deg2[N_NODES];     // fill pass cursors (pre-zeroed)
__device__ int   g_cnt2[N_HEDGES];
__device__ int   g_nptr[N_NODES + 1];
__device__ int   g_hptr[N_HEDGES + 1];
__device__ int   g_bsumN[128];
__device__ int   g_bsumH[16];
__device__ int   g_node_hedges[NNZ];   // per-node list of hyperedge ids
__device__ int   g_hedge_nodes[NNZ];   // per-hyperedge list of node ids
__device__ float g_dinv[N_NODES];
__device__ float g_binv[N_HEDGES];
__device__ float g_e1 [(size_t)N_HEDGES * IN_C];   // Binv * H^T x
__device__ float g_ew1[(size_t)N_HEDGES * D1];     // e1 @ W1
__device__ float g_hw [(size_t)N_NODES * D2];      // h @ W2 (h never materialized)
__device__ float g_e2 [(size_t)N_HEDGES * D2];

// ---------------- CSR build (6 launches total) ----------------
__global__ void k_zero() {
    int i = blockIdx.x * blockDim.x + threadIdx.x;
    if (i < N_NODES)  { g_deg[i] = 0; g_deg2[i] = 0; }
    if (i < N_HEDGES) { g_cnt[i] = 0; g_cnt2[i] = 0; }
}

__global__ void k_count(const int* __restrict__ nidx, const int* __restrict__ hidx) {
    int i = blockIdx.x * blockDim.x + threadIdx.x;
    if (i >= NNZ) return;
    atomicAdd(&g_deg[nidx[i]], 1);
    atomicAdd(&g_cnt[hidx[i]], 1);
}

// one grid handles both arrays: blocks [0,NB_N) -> nodes, [NB_N,NB_N+NB_H) -> hedges
__global__ void k_bsum_both() {
    int b = blockIdx.x;
    const int* in; int n; int* bs;
    if (b < NB_N) { in = g_deg; n = N_NODES;  bs = g_bsumN; }
    else          { b -= NB_N; in = g_cnt; n = N_HEDGES; bs = g_bsumH; }
    __shared__ int s[512];
    int t = threadIdx.x, i = b * 512 + t;
    s[t] = (i < n) ? in[i] : 0;
    __syncthreads();
    for (int off = 256; off > 0; off >>= 1) {
        if (t < off) s[t] += s[t + off];
        __syncthreads();
    }
    if (t == 0) bs[b] = s[0];
}

__global__ void k_scan_small_both() {   // exclusive scan of both block-sum arrays
    __shared__ int s[1024];
    int t = threadIdx.x;
    // nodes
    {
        int v = (t < NB_N) ? g_bsumN[t] : 0;
        s[t] = v;
        __syncthreads();
        for (int off = 1; off < 1024; off <<= 1) {
            int x = (t >= off) ? s[t - off] : 0;
            __syncthreads();
            s[t] += x;
            __syncthreads();
        }
        if (t < NB_N) g_bsumN[t] = s[t] - v;
        __syncthreads();
    }
    // hedges
    {
        int v = (t < NB_H) ? g_bsumH[t] : 0;
        s[t] = v;
        __syncthreads();
        for (int off = 1; off < 1024; off <<= 1) {
            int x = (t >= off) ? s[t - off] : 0;
            __syncthreads();
            s[t] += x;
            __syncthreads();
        }
        if (t < NB_H) g_bsumH[t] = s[t] - v;
    }
}

// final scan + row-pointer write + inverse-degree write (k_inv folded in)
__global__ void k_scan_final_both() {
    int b = blockIdx.x;
    const int* in; const int* boff; int* ptr; int n; float* inv;
    if (b < NB_N) { in = g_deg; boff = g_bsumN; ptr = g_nptr; n = N_NODES;  inv = g_dinv; }
    else          { b -= NB_N; in = g_cnt; boff = g_bsumH; ptr = g_hptr; n = N_HEDGES; inv = g_binv; }
    __shared__ int s[512];
    int t = threadIdx.x, i = b * 512 + t;
    int v = (i < n) ? in[i] : 0;
    s[t] = v;
    __syncthreads();
    for (int off = 1; off < 512; off <<= 1) {
        int x = (t >= off) ? s[t - off] : 0;
        __syncthreads();
        s[t] += x;
        __syncthreads();
    }
    int excl = s[t] - v + boff[b];
    if (i < n) {
        ptr[i] = excl;
        inv[i] = v ? 1.0f / (float)v : 0.0f;
    }
    if (i == n - 1) ptr[n] = excl + v;
}

__global__ void k_fill(const int* __restrict__ nidx, const int* __restrict__ hidx) {
    int i = blockIdx.x * blockDim.x + threadIdx.x;
    if (i >= NNZ) return;
    int n = nidx[i], e = hidx[i];
    int p = atomicAdd(&g_deg2[n], 1);
    g_node_hedges[g_nptr[n] + p] = e;
    int q = atomicAdd(&g_cnt2[e], 1);
    g_hedge_nodes[g_hptr[e] + q] = n;
}

// ---------------- aggregation (CSR, no atomics) ----------------
// hyperedge e: e1[e,:] = Binv[e] * sum_{n in e} x[n,:]  (128 dims, warp/hedge, 4-way MLP)
__global__ void k_hedge_agg128(const float* __restrict__ x) {
    int w = (blockIdx.x * blockDim.x + threadIdx.x) >> 5;
    if (w >= N_HEDGES) return;
    int lane = threadIdx.x & 31;
    int beg = g_hptr[w], end = g_hptr[w + 1];
    float4 a0 = make_float4(0.f,0.f,0.f,0.f), a1 = a0, a2 = a0, a3 = a0;
    int j = beg;
    for (; j + 3 < end; j += 4) {
        int n0 = g_hedge_nodes[j],     n1 = g_hedge_nodes[j + 1];
        int n2 = g_hedge_nodes[j + 2], n3 = g_hedge_nodes[j + 3];
        float4 v0 = *(const float4*)(x + (size_t)n0 * IN_C + lane * 4);
        float4 v1 = *(const float4*)(x + (size_t)n1 * IN_C + lane * 4);
        float4 v2 = *(const float4*)(x + (size_t)n2 * IN_C + lane * 4);
        float4 v3 = *(const float4*)(x + (size_t)n3 * IN_C + lane * 4);
        a0.x += v0.x; a0.y += v0.y; a0.z += v0.z; a0.w += v0.w;
        a1.x += v1.x; a1.y += v1.y; a1.z += v1.z; a1.w += v1.w;
        a2.x += v2.x; a2.y += v2.y; a2.z += v2.z; a2.w += v2.w;
        a3.x += v3.x; a3.y += v3.y; a3.z += v3.z; a3.w += v3.w;
    }
    for (; j < end; j++) {
        int n0 = g_hedge_nodes[j];
        float4 v0 = *(const float4*)(x + (size_t)n0 * IN_C + lane * 4);
        a0.x += v0.x; a0.y += v0.y; a0.z += v0.z; a0.w += v0.w;
    }
    float s = g_binv[w];
    float4 o;
    o.x = (a0.x + a1.x + a2.x + a3.x) * s;
    o.y = (a0.y + a1.y + a2.y + a3.y) * s;
    o.z = (a0.z + a1.z + a2.z + a3.z) * s;
    o.w = (a0.w + a1.w + a2.w + a3.w) * s;
    *(float4*)(g_e1 + (size_t)w * IN_C + lane * 4) = o;
}

// ---- fused: node-aggregate ew1 @256 (+Dinv+b1+relu) into smem, then GEMM with W2 ----
// block = 32 nodes, 256 threads. hw[32,64] written; h never touches gmem.
__global__ void k_agg256_gemm2(const float* __restrict__ b1, const float* __restrict__ W2) {
    __shared__ float Hs[32][260];   // h tile, row-major, padded
    __shared__ float Bs[16][64];    // W2 k-slice
    int tid = threadIdx.x;
    int warp = tid >> 5, lane = tid & 31;
    int blockNode = blockIdx.x * 32;

    // phase 1: each warp aggregates 4 nodes
    #pragma unroll
    for (int i = 0; i < 4; i++) {
        int m = warp * 4 + i;
        int node = blockNode + m;
        float4 a0 = make_float4(0.f,0.f,0.f,0.f);
        float4 a1 = make_float4(0.f,0.f,0.f,0.f);
        if (node < N_NODES) {
            int beg = g_nptr[node], end = g_nptr[node + 1];
            int j = beg;
            for (; j + 1 < end; j += 2) {      // 4 independent float4 loads in flight
                int e0 = g_node_hedges[j], e1 = g_node_hedges[j + 1];
                const float4* p0 = (const float4*)(g_ew1 + (size_t)e0 * D1) + lane;
                const float4* p1 = (const float4*)(g_ew1 + (size_t)e1 * D1) + lane;
                float4 v00 = p0[0], v01 = p0[32];
                float4 v10 = p1[0], v11 = p1[32];
                a0.x += v00.x + v10.x; a0.y += v00.y + v10.y;
                a0.z += v00.z + v10.z; a0.w += v00.w + v10.w;
                a1.x += v01.x + v11.x; a1.y += v01.y + v11.y;
                a1.z += v01.z + v11.z; a1.w += v01.w + v11.w;
            }
            if (j < end) {
                int e0 = g_node_hedges[j];
                const float4* p0 = (const float4*)(g_ew1 + (size_t)e0 * D1) + lane;
                float4 v00 = p0[0], v01 = p0[32];
                a0.x += v00.x; a0.y += v00.y; a0.z += v00.z; a0.w += v00.w;
                a1.x += v01.x; a1.y += v01.y; a1.z += v01.z; a1.w += v01.w;
            }
            float di = g_dinv[node];
            float4 bA = *(const float4*)(b1 + lane * 4);
            float4 bB = *(const float4*)(b1 + 128 + lane * 4);
            a0.x = fmaxf(a0.x * di + bA.x, 0.f); a0.y = fmaxf(a0.y * di + bA.y, 0.f);
            a0.z = fmaxf(a0.z * di + bA.z, 0.f); a0.w = fmaxf(a0.w * di + bA.w, 0.f);
            a1.x = fmaxf(a1.x * di + bB.x, 0.f); a1.y = fmaxf(a1.y * di + bB.y, 0.f);
            a1.z = fmaxf(a1.z * di + bB.z, 0.f); a1.w = fmaxf(a1.w * di + bB.w, 0.f);
        }
        *(float4*)&Hs[m][lane * 4]       = a0;
        *(float4*)&Hs[m][128 + lane * 4] = a1;
    }
    __syncthreads();

    // phase 2: hw_tile[32,64] = Hs[32,256] @ W2[256,64]
    int tr = (tid >> 4) << 1;      // 2 rows
    int tc = (tid & 15) << 2;      // 4 cols
    float acc[2][4] = {};
    for (int k0 = 0; k0 < D1; k0 += 16) {
        #pragma unroll
        for (int i = 0; i < 4; i++) {
            int idx = tid + i * 256;
            int kk = idx >> 6, n = idx & 63;
            Bs[kk][n] = W2[(size_t)(k0 + kk) * D2 + n];
        }
        __syncthreads();
        #pragma unroll
        for (int kk = 0; kk < 16; kk++) {
            float a0 = Hs[tr][k0 + kk];       // broadcast within half-warp
            float a1 = Hs[tr + 1][k0 + kk];
            float4 b = *(const float4*)&Bs[kk][tc];
            acc[0][0] += a0 * b.x; acc[0][1] += a0 * b.y; acc[0][2] += a0 * b.z; acc[0][3] += a0 * b.w;
            acc[1][0] += a1 * b.x; acc[1][1] += a1 * b.y; acc[1][2] += a1 * b.z; acc[1][3] += a1 * b.w;
        }
        __syncthreads();
    }
    #pragma unroll
    for (int i = 0; i < 2; i++) {
        int node = blockNode + tr + i;
        if (node < N_NODES) {
            float4 o = make_float4(acc[i][0], acc[i][1], acc[i][2], acc[i][3]);
            *(float4*)(g_hw + (size_t)node * D2 + tc) = o;
        }
    }
}

// hyperedge e: e2[e,:] = Binv[e] * sum_{n in e} hw[n,:]  (64 dims, 4-way MLP)
__global__ void k_hedge_agg64() {
    int w = (blockIdx.x * blockDim.x + threadIdx.x) >> 5;
    if (w >= N_HEDGES) return;
    int lane = threadIdx.x & 31;
    int beg = g_hptr[w], end = g_hptr[w + 1];
    float2 a0 = make_float2(0.f,0.f), a1 = a0, a2 = a0, a3 = a0;
    int j = beg;
    for (; j + 3 < end; j += 4) {
        int n0 = g_hedge_nodes[j],     n1 = g_hedge_nodes[j + 1];
        int n2 = g_hedge_nodes[j + 2], n3 = g_hedge_nodes[j + 3];
        float2 v0 = *(const float2*)(g_hw + (size_t)n0 * D2 + lane * 2);
        float2 v1 = *(const float2*)(g_hw + (size_t)n1 * D2 + lane * 2);
        float2 v2 = *(const float2*)(g_hw + (size_t)n2 * D2 + lane * 2);
        float2 v3 = *(const float2*)(g_hw + (size_t)n3 * D2 + lane * 2);
        a0.x += v0.x; a0.y += v0.y;
        a1.x += v1.x; a1.y += v1.y;
        a2.x += v2.x; a2.y += v2.y;
        a3.x += v3.x; a3.y += v3.y;
    }
    for (; j < end; j++) {
        int n0 = g_hedge_nodes[j];
        float2 v0 = *(const float2*)(g_hw + (size_t)n0 * D2 + lane * 2);
        a0.x += v0.x; a0.y += v0.y;
    }
    float s = g_binv[w];
    float2 o = make_float2((a0.x + a1.x + a2.x + a3.x) * s,
                           (a0.y + a1.y + a2.y + a3.y) * s);
    *(float2*)(g_e2 + (size_t)w * D2 + lane * 2) = o;
}

// node n: out[n,:] = relu(Dinv[n] * sum_{e of n} e2[e,:] + b2)
__global__ void k_node_agg64_out(const float* __restrict__ b2, float* __restrict__ out) {
    int w = (blockIdx.x * blockDim.x + threadIdx.x) >> 5;
    if (w >= N_NODES) return;
    int lane = threadIdx.x & 31;
    int beg = g_nptr[w], end = g_nptr[w + 1];
    float2 a0 = make_float2(0.f,0.f), a1 = a0, a2 = a0, a3 = a0;
    int j = beg;
    for (; j + 3 < end; j += 4) {
        int e0 = g_node_hedges[j],     e1 = g_node_hedges[j + 1];
        int e2i = g_node_hedges[j + 2], e3 = g_node_hedges[j + 3];
        float2 v0 = *(const float2*)(g_e2 + (size_t)e0 * D2 + lane * 2);
        float2 v1 = *(const float2*)(g_e2 + (size_t)e1 * D2 + lane * 2);
        float2 v2 = *(const float2*)(g_e2 + (size_t)e2i * D2 + lane * 2);
        float2 v3 = *(const float2*)(g_e2 + (size_t)e3 * D2 + lane * 2);
        a0.x += v0.x; a0.y += v0.y;
        a1.x += v1.x; a1.y += v1.y;
        a2.x += v2.x; a2.y += v2.y;
        a3.x += v3.x; a3.y += v3.y;
    }
    for (; j < end; j++) {
        int e0 = g_node_hedges[j];
        float2 v0 = *(const float2*)(g_e2 + (size_t)e0 * D2 + lane * 2);
        a0.x += v0.x; a0.y += v0.y;
    }
    float di = g_dinv[w];
    float2 bb = *(const float2*)(b2 + lane * 2);
    float o0 = fmaxf((a0.x + a1.x + a2.x + a3.x) * di + bb.x, 0.f);
    float o1 = fmaxf((a0.y + a1.y + a2.y + a3.y) * di + bb.y, 0.f);
    *(float2*)(out + (size_t)w * D2 + lane * 2) = make_float2(o0, o1);
}

// ---------------- tiled fp32 GEMM (hedge-side only): C[M,N] = A[M,K] @ B[K,N] ----------------
__global__ void k_gemm_e1(const float* __restrict__ W1) {
    const float* A = g_e1;
    const float* B = W1;
    float* C = g_ew1;
    const int M = N_HEDGES, N = D1, K = IN_C;
    constexpr int BM = 64, BN = 64, BK = 16;
    __shared__ float As[BK][BM + 4];
    __shared__ float Bs[BK][BN];
    int bm = blockIdx.y * BM, bn = blockIdx.x * BN;
    int tid = threadIdx.x;
    int tr = (tid >> 4) << 2;
    int tc = (tid & 15) << 2;
    float acc[4][4] = {};
    for (int k0 = 0; k0 < K; k0 += BK) {
        #pragma unroll
        for (int i = 0; i < 4; i++) {
            int idx = tid + i * 256;
            int m = idx >> 4, kk = idx & 15;
            int gm = bm + m;
            As[kk][m] = (gm < M) ? A[(size_t)gm * K + k0 + kk] : 0.f;
        }
        #pragma unroll
        for (int i = 0; i < 4; i++) {
            int idx = tid + i * 256;
            int kk = idx >> 6, n = idx & 63;
            Bs[kk][n] = B[(size_t)(k0 + kk) * N + bn + n];
        }
        __syncthreads();
        #pragma unroll
        for (int kk = 0; kk < BK; kk++) {
            float4 a = *(const float4*)&As[kk][tr];
            float4 b = *(const float4*)&Bs[kk][tc];
            acc[0][0] += a.x * b.x; acc[0][1] += a.x * b.y; acc[0][2] += a.x * b.z; acc[0][3] += a.x * b.w;
            acc[1][0] += a.y * b.x; acc[1][1] += a.y * b.y; acc[1][2] += a.y * b.z; acc[1][3] += a.y * b.w;
            acc[2][0] += a.z * b.x; acc[2][1] += a.z * b.y; acc[2][2] += a.z * b.z; acc[2][3] += a.z * b.w;
            acc[3][0] += a.w * b.x; acc[3][1] += a.w * b.y; acc[3][2] += a.w * b.z; acc[3][3] += a.w * b.w;
        }
        __syncthreads();
    }
    #pragma unroll
    for (int i = 0; i < 4; i++) {
        int gm = bm + tr + i;
        if (gm >= M) continue;
        #pragma unroll
        for (int j = 0; j < 4; j++) {
            C[(size_t)gm * N + bn + tc + j] = acc[i][j];
        }
    }
}

// ---------------- launch ----------------
extern "C" void kernel_launch(void* const* d_in, const int* in_sizes, int n_in,
                              void* d_out, int out_size) {
    const float* x  = (const float*)d_in[0];
    const int* edge = (const int*)d_in[1];
    const float* W1 = (const float*)d_in[2];
    const float* b1 = (const float*)d_in[3];
    const float* W2 = (const float*)d_in[4];
    const float* b2 = (const float*)d_in[5];
    float* out = (float*)d_out;
    const int* nidx = edge;
    const int* hidx = edge + NNZ;

    // CSR build (6 launches)
    k_zero<<<(N_NODES + 255) / 256, 256>>>();
    k_count<<<(NNZ + 255) / 256, 256>>>(nidx, hidx);
    k_bsum_both<<<NB_N + NB_H, 512>>>();
    k_scan_small_both<<<1, 1024>>>();
    k_scan_final_both<<<NB_N + NB_H, 512>>>();
    k_fill<<<(NNZ + 255) / 256, 256>>>(nidx, hidx);

    // Layer 1: hedge agg @128 -> hedge-side GEMM -> fused node-agg@256 + GEMM2
    k_hedge_agg128<<<(N_HEDGES * 32 + 255) / 256, 256>>>(x);
    {
        dim3 grid(D1 / 64, (N_HEDGES + 63) / 64);
        k_gemm_e1<<<grid, 256>>>(W1);
    }
    k_agg256_gemm2<<<(N_NODES + 31) / 32, 256>>>(b1, W2);

    // Layer 2 tail: down @64, up @64 with fused epilogue
    k_hedge_agg64<<<(N_HEDGES * 32 + 255) / 256, 256>>>();
    k_node_agg64_out<<<(N_NODES * 32 + 255) / 256, 256>>>(b2, out);
}

// round 10
// speedup vs baseline: 1.3906x; 1.1095x over previous
#include <cuda_runtime.h>
#include <cuda_bf16.h>
#include <cstdint>

#define N_NODES  50000
#define N_HEDGES 5000
#define NNZ      800000
#define IN_C     128
#define D1       256
#define D2       64

#define NB_N 98   // ceil(50000/512)
#define NB_H 10   // ceil(5000/512)

// ---------------- scratch (static device memory; no allocation) ----------------
__device__ int   g_deg [N_NODES];     // count pass
__device__ int   g_cnt [N_HEDGES];
__device__ int   g_deg2[N_NODES];     // fill cursors (zeroed in scan kernel)
__device__ int   g_cnt2[N_HEDGES];
__device__ int   g_nptr[N_NODES + 1];
__device__ int   g_hptr[N_HEDGES + 1];
__device__ unsigned g_bsum[NB_N + NB_H];   // bit31 = ready flag (stale-safe: values identical each run)
__device__ int   g_node_hedges[NNZ];
__device__ int   g_hedge_nodes[NNZ];
__device__ float g_dinv[N_NODES];
__device__ float g_binv[N_HEDGES];
__device__ __nv_bfloat16 g_xb [(size_t)N_NODES * IN_C];   // x in bf16
__device__ float g_e1 [(size_t)N_HEDGES * IN_C];          // Binv * H^T x  (fp32, read once by GEMM)
__device__ __nv_bfloat16 g_ew1[(size_t)N_HEDGES * D1];    // e1 @ W1      (bf16, heavy gather)
__device__ __nv_bfloat16 g_hw [(size_t)N_NODES * D2];     // h @ W2       (bf16)
__device__ __nv_bfloat16 g_e2 [(size_t)N_HEDGES * D2];    // bf16

__device__ __forceinline__ void bf2x(unsigned u, float& a, float& b) {
    a = __uint_as_float(u << 16);
    b = __uint_as_float(u & 0xffff0000u);
}

// ---------------- prep: zero counters + convert x to bf16 ----------------
__global__ void k_prep(const float* __restrict__ x) {
    int i = blockIdx.x * blockDim.x + threadIdx.x;   // 1.6M threads
    if (i < N_NODES)  g_deg[i] = 0;
    if (i < N_HEDGES) g_cnt[i] = 0;
    int base = i * 4;
    if (base < N_NODES * IN_C) {
        float4 v = *(const float4*)(x + base);
        *(__nv_bfloat162*)(g_xb + base)     = __floats2bfloat162_rn(v.x, v.y);
        *(__nv_bfloat162*)(g_xb + base + 2) = __floats2bfloat162_rn(v.z, v.w);
    }
}

__global__ void k_count(const int* __restrict__ nidx, const int* __restrict__ hidx) {
    int i = blockIdx.x * blockDim.x + threadIdx.x;
    if (i >= NNZ) return;
    atomicAdd(&g_deg[nidx[i]], 1);
    atomicAdd(&g_cnt[hidx[i]], 1);
}

// ---------------- single-kernel scan (108 co-resident blocks, flag-polling) ----------------
__global__ void k_scan() {
    __shared__ int s[512];
    __shared__ int red[512];
    int b = blockIdx.x, t = threadIdx.x;
    bool isNode = (b < NB_N);
    int lb        = isNode ? b : b - NB_N;
    int segBase   = isNode ? 0 : NB_N;
    const int* in = isNode ? g_deg  : g_cnt;
    int n         = isNode ? N_NODES : N_HEDGES;
    int* ptr      = isNode ? g_nptr : g_hptr;
    float* inv    = isNode ? g_dinv : g_binv;
    int* cur      = isNode ? g_deg2 : g_cnt2;

    int i = lb * 512 + t;
    int v = (i < n) ? in[i] : 0;
    s[t] = v;
    __syncthreads();
    for (int off = 1; off < 512; off <<= 1) {
        int x = (t >= off) ? s[t - off] : 0;
        __syncthreads();
        s[t] += x;
        __syncthreads();
    }
    int incl = s[t];
    int total = s[511];
    if (t == 0)
        *(volatile unsigned*)&g_bsum[b] = ((unsigned)total) | 0x80000000u;

    // exclusive prefix over preceding blocks of this segment
    int mine = 0;
    if (t < lb) {
        volatile unsigned* p = (volatile unsigned*)&g_bsum[segBase + t];
        unsigned u;
        do { u = *p; } while (!(u & 0x80000000u));
        mine = (int)(u & 0x7FFFFFFFu);
    }
    red[t] = mine;
    __syncthreads();
    for (int off = 256; off > 0; off >>= 1) {
        if (t < off) red[t] += red[t + off];
        __syncthreads();
    }
    int excl = incl - v + red[0];
    if (i < n) {
        ptr[i] = excl;
        inv[i] = v ? 1.0f / (float)v : 0.0f;
        cur[i] = 0;
    }
    if (i == n - 1) ptr[n] = excl + v;
}

__global__ void k_fill(const int* __restrict__ nidx, const int* __restrict__ hidx) {
    int i = blockIdx.x * blockDim.x + threadIdx.x;
    if (i >= NNZ) return;
    int n = nidx[i], e = hidx[i];
    int p = atomicAdd(&g_deg2[n], 1);
    g_node_hedges[g_nptr[n] + p] = e;
    int q = atomicAdd(&g_cnt2[e], 1);
    g_hedge_nodes[g_hptr[e] + q] = n;
}

// ---------------- aggregation (CSR, no atomics, bf16 gathers) ----------------
// hyperedge e: e1[e,:] = Binv[e] * sum_{n in e} xb[n,:]  (128 dims, lane = 4 cols, 4-way MLP)
__global__ void k_hedge_agg128() {
    int w = (blockIdx.x * blockDim.x + threadIdx.x) >> 5;
    if (w >= N_HEDGES) return;
    int lane = threadIdx.x & 31;
    int beg = g_hptr[w], end = g_hptr[w + 1];
    float a0 = 0.f, a1 = 0.f, a2 = 0.f, a3 = 0.f;
    float b0 = 0.f, b1 = 0.f, b2 = 0.f, b3 = 0.f;
    float c0 = 0.f, c1 = 0.f, c2 = 0.f, c3 = 0.f;
    float d0 = 0.f, d1 = 0.f, d2 = 0.f, d3 = 0.f;
    int j = beg;
    for (; j + 3 < end; j += 4) {
        int n0 = g_hedge_nodes[j],     n1 = g_hedge_nodes[j + 1];
        int n2 = g_hedge_nodes[j + 2], n3 = g_hedge_nodes[j + 3];
        uint2 u0 = *((const uint2*)(g_xb + (size_t)n0 * IN_C) + lane);
        uint2 u1 = *((const uint2*)(g_xb + (size_t)n1 * IN_C) + lane);
        uint2 u2 = *((const uint2*)(g_xb + (size_t)n2 * IN_C) + lane);
        uint2 u3 = *((const uint2*)(g_xb + (size_t)n3 * IN_C) + lane);
        float x0, x1, x2, x3;
        bf2x(u0.x, x0, x1); bf2x(u0.y, x2, x3); a0 += x0; a1 += x1; a2 += x2; a3 += x3;
        bf2x(u1.x, x0, x1); bf2x(u1.y, x2, x3); b0 += x0; b1 += x1; b2 += x2; b3 += x3;
        bf2x(u2.x, x0, x1); bf2x(u2.y, x2, x3); c0 += x0; c1 += x1; c2 += x2; c3 += x3;
        bf2x(u3.x, x0, x1); bf2x(u3.y, x2, x3); d0 += x0; d1 += x1; d2 += x2; d3 += x3;
    }
    for (; j < end; j++) {
        int n0 = g_hedge_nodes[j];
        uint2 u0 = *((const uint2*)(g_xb + (size_t)n0 * IN_C) + lane);
        float x0, x1, x2, x3;
        bf2x(u0.x, x0, x1); bf2x(u0.y, x2, x3); a0 += x0; a1 += x1; a2 += x2; a3 += x3;
    }
    float sc = g_binv[w];
    float4 o;
    o.x = (a0 + b0 + c0 + d0) * sc;
    o.y = (a1 + b1 + c1 + d1) * sc;
    o.z = (a2 + b2 + c2 + d2) * sc;
    o.w = (a3 + b3 + c3 + d3) * sc;
    *(float4*)(g_e1 + (size_t)w * IN_C + lane * 4) = o;
}

// ---- fused: node-aggregate ew1 (bf16) @256 (+Dinv+b1+relu) into smem, then GEMM with W2 ----
__global__ void k_agg256_gemm2(const float* __restrict__ b1, const float* __restrict__ W2) {
    __shared__ float Hs[32][260];
    __shared__ float Bs[16][64];
    int tid = threadIdx.x;
    int warp = tid >> 5, lane = tid & 31;
    int blockNode = blockIdx.x * 32;
    int base = lane * 8;   // 8 columns per lane

    #pragma unroll
    for (int i = 0; i < 4; i++) {
        int m = warp * 4 + i;
        int node = blockNode + m;
        float f[8] = {};
        if (node < N_NODES) {
            int beg = g_nptr[node], end = g_nptr[node + 1];
            int j = beg;
            for (; j + 1 < end; j += 2) {
                int e0 = g_node_hedges[j], e1 = g_node_hedges[j + 1];
                uint4 u0 = *((const uint4*)(g_ew1 + (size_t)e0 * D1) + lane);
                uint4 u1 = *((const uint4*)(g_ew1 + (size_t)e1 * D1) + lane);
                float p, q;
                bf2x(u0.x, p, q); f[0] += p; f[1] += q;
                bf2x(u0.y, p, q); f[2] += p; f[3] += q;
                bf2x(u0.z, p, q); f[4] += p; f[5] += q;
                bf2x(u0.w, p, q); f[6] += p; f[7] += q;
                bf2x(u1.x, p, q); f[0] += p; f[1] += q;
                bf2x(u1.y, p, q); f[2] += p; f[3] += q;
                bf2x(u1.z, p, q); f[4] += p; f[5] += q;
                bf2x(u1.w, p, q); f[6] += p; f[7] += q;
            }
            if (j < end) {
                int e0 = g_node_hedges[j];
                uint4 u0 = *((const uint4*)(g_ew1 + (size_t)e0 * D1) + lane);
                float p, q;
                bf2x(u0.x, p, q); f[0] += p; f[1] += q;
                bf2x(u0.y, p, q); f[2] += p; f[3] += q;
                bf2x(u0.z, p, q); f[4] += p; f[5] += q;
                bf2x(u0.w, p, q); f[6] += p; f[7] += q;
            }
            float di = g_dinv[node];
            float4 bA = *(const float4*)(b1 + base);
            float4 bB = *(const float4*)(b1 + base + 4);
            f[0] = fmaxf(f[0] * di + bA.x, 0.f); f[1] = fmaxf(f[1] * di + bA.y, 0.f);
            f[2] = fmaxf(f[2] * di + bA.z, 0.f); f[3] = fmaxf(f[3] * di + bA.w, 0.f);
            f[4] = fmaxf(f[4] * di + bB.x, 0.f); f[5] = fmaxf(f[5] * di + bB.y, 0.f);
            f[6] = fmaxf(f[6] * di + bB.z, 0.f); f[7] = fmaxf(f[7] * di + bB.w, 0.f);
        }
        *(float4*)&Hs[m][base]     = make_float4(f[0], f[1], f[2], f[3]);
        *(float4*)&Hs[m][base + 4] = make_float4(f[4], f[5], f[6], f[7]);
    }
    __syncthreads();

    // phase 2: hw_tile[32,64] = Hs[32,256] @ W2[256,64], store bf16
    int tr = (tid >> 4) << 1;
    int tc = (tid & 15) << 2;
    float acc[2][4] = {};
    for (int k0 = 0; k0 < D1; k0 += 16) {
        #pragma unroll
        for (int i = 0; i < 4; i++) {
            int idx = tid + i * 256;
            int kk = idx >> 6, n = idx & 63;
            Bs[kk][n] = W2[(size_t)(k0 + kk) * D2 + n];
        }
        __syncthreads();
        #pragma unroll
        for (int kk = 0; kk < 16; kk++) {
            float a0 = Hs[tr][k0 + kk];
            float a1 = Hs[tr + 1][k0 + kk];
            float4 b = *(const float4*)&Bs[kk][tc];
            acc[0][0] += a0 * b.x; acc[0][1] += a0 * b.y; acc[0][2] += a0 * b.z; acc[0][3] += a0 * b.w;
            acc[1][0] += a1 * b.x; acc[1][1] += a1 * b.y; acc[1][2] += a1 * b.z; acc[1][3] += a1 * b.w;
        }
        __syncthreads();
    }
    #pragma unroll
    for (int i = 0; i < 2; i++) {
        int node = blockNode + tr + i;
        if (node < N_NODES) {
            *(__nv_bfloat162*)(g_hw + (size_t)node * D2 + tc)     = __floats2bfloat162_rn(acc[i][0], acc[i][1]);
            *(__nv_bfloat162*)(g_hw + (size_t)node * D2 + tc + 2) = __floats2bfloat162_rn(acc[i][2], acc[i][3]);
        }
    }
}

// hyperedge e: e2[e,:] = Binv[e] * sum hw[n,:]  (64 dims bf16, lane = 2 cols, 4-way MLP)
__global__ void k_hedge_agg64() {
    int w = (blockIdx.x * blockDim.x + threadIdx.x) >> 5;
    if (w >= N_HEDGES) return;
    int lane = threadIdx.x & 31;
    int beg = g_hptr[w], end = g_hptr[w + 1];
    float a0 = 0.f, a1 = 0.f, b0 = 0.f, b1 = 0.f;
    float c0 = 0.f, c1 = 0.f, d0 = 0.f, d1 = 0.f;
    int j = beg;
    for (; j + 3 < end; j += 4) {
        int n0 = g_hedge_nodes[j],     n1 = g_hedge_nodes[j + 1];
        int n2 = g_hedge_nodes[j + 2], n3 = g_hedge_nodes[j + 3];
        unsigned u0 = *((const unsigned*)(g_hw + (size_t)n0 * D2) + lane);
        unsigned u1 = *((const unsigned*)(g_hw + (size_t)n1 * D2) + lane);
        unsigned u2 = *((const unsigned*)(g_hw + (size_t)n2 * D2) + lane);
        unsigned u3 = *((const unsigned*)(g_hw + (size_t)n3 * D2) + lane);
        float p, q;
        bf2x(u0, p, q); a0 += p; a1 += q;
        bf2x(u1, p, q); b0 += p; b1 += q;
        bf2x(u2, p, q); c0 += p; c1 += q;
        bf2x(u3, p, q); d0 += p; d1 += q;
    }
    for (; j < end; j++) {
        int n0 = g_hedge_nodes[j];
        unsigned u0 = *((const unsigned*)(g_hw + (size_t)n0 * D2) + lane);
        float p, q;
        bf2x(u0, p, q); a0 += p; a1 += q;
    }
    float sc = g_binv[w];
    float sx = (a0 + b0 + c0 + d0) * sc;
    float sy = (a1 + b1 + c1 + d1) * sc;
    *(__nv_bfloat162*)(g_e2 + (size_t)w * D2 + lane * 2) = __floats2bfloat162_rn(sx, sy);
}

// node n: out[n,:] = relu(Dinv[n] * sum e2[e,:] + b2)  (fp32 out)
__global__ void k_node_agg64_out(const float* __restrict__ b2, float* __restrict__ out) {
    int w = (blockIdx.x * blockDim.x + threadIdx.x) >> 5;
    if (w >= N_NODES) return;
    int lane = threadIdx.x & 31;
    int beg = g_nptr[w], end = g_nptr[w + 1];
    float a0 = 0.f, a1 = 0.f, b0 = 0.f, b1 = 0.f;
    float c0 = 0.f, c1 = 0.f, d0 = 0.f, d1 = 0.f;
    int j = beg;
    for (; j + 3 < end; j += 4) {
        int e0 = g_node_hedges[j],     e1i = g_node_hedges[j + 1];
        int e2i = g_node_hedges[j + 2], e3 = g_node_hedges[j + 3];
        unsigned u0 = *((const unsigned*)(g_e2 + (size_t)e0  * D2) + lane);
        unsigned u1 = *((const unsigned*)(g_e2 + (size_t)e1i * D2) + lane);
        unsigned u2 = *((const unsigned*)(g_e2 + (size_t)e2i * D2) + lane);
        unsigned u3 = *((const unsigned*)(g_e2 + (size_t)e3  * D2) + lane);
        float p, q;
        bf2x(u0, p, q); a0 += p; a1 += q;
        bf2x(u1, p, q); b0 += p; b1 += q;
        bf2x(u2, p, q); c0 += p; c1 += q;
        bf2x(u3, p, q); d0 += p; d1 += q;
    }
    for (; j < end; j++) {
        int e0 = g_node_hedges[j];
        unsigned u0 = *((const unsigned*)(g_e2 + (size_t)e0 * D2) + lane);
        float p, q;
        bf2x(u0, p, q); a0 += p; a1 += q;
    }
    float di = g_dinv[w];
    float2 bb = *(const float2*)(b2 + lane * 2);
    float o0 = fmaxf((a0 + b0 + c0 + d0) * di + bb.x, 0.f);
    float o1 = fmaxf((a1 + b1 + c1 + d1) * di + bb.y, 0.f);
    *(float2*)(out + (size_t)w * D2 + lane * 2) = make_float2(o0, o1);
}

// ---------------- hedge-side GEMM: ew1 = e1 @ W1, bf16 out ----------------
__global__ void k_gemm_e1(const float* __restrict__ W1) {
    const float* A = g_e1;
    const float* B = W1;
    const int M = N_HEDGES, N = D1, K = IN_C;
    constexpr int BM = 64, BN = 64, BK = 16;
    __shared__ float As[BK][BM + 4];
    __shared__ float Bs[BK][BN];
    int bm = blockIdx.y * BM, bn = blockIdx.x * BN;
    int tid = threadIdx.x;
    int tr = (tid >> 4) << 2;
    int tc = (tid & 15) << 2;
    float acc[4][4] = {};
    for (int k0 = 0; k0 < K; k0 += BK) {
        #pragma unroll
        for (int i = 0; i < 4; i++) {
            int idx = tid + i * 256;
            int m = idx >> 4, kk = idx & 15;
            int gm = bm + m;
            As[kk][m] = (gm < M) ? A[(size_t)gm * K + k0 + kk] : 0.f;
        }
        #pragma unroll
        for (int i = 0; i < 4; i++) {
            int idx = tid + i * 256;
            int kk = idx >> 6, n = idx & 63;
            Bs[kk][n] = B[(size_t)(k0 + kk) * N + bn + n];
        }
        __syncthreads();
        #pragma unroll
        for (int kk = 0; kk < BK; kk++) {
            float4 a = *(const float4*)&As[kk][tr];
            float4 b = *(const float4*)&Bs[kk][tc];
            acc[0][0] += a.x * b.x; acc[0][1] += a.x * b.y; acc[0][2] += a.x * b.z; acc[0][3] += a.x * b.w;
            acc[1][0] += a.y * b.x; acc[1][1] += a.y * b.y; acc[1][2] += a.y * b.z; acc[1][3] += a.y * b.w;
            acc[2][0] += a.z * b.x; acc[2][1] += a.z * b.y; acc[2][2] += a.z * b.z; acc[2][3] += a.z * b.w;
            acc[3][0] += a.w * b.x; acc[3][1] += a.w * b.y; acc[3][2] += a.w * b.z; acc[3][3] += a.w * b.w;
        }
        __syncthreads();
    }
    #pragma unroll
    for (int i = 0; i < 4; i++) {
        int gm = bm + tr + i;
        if (gm >= M) continue;
        __nv_bfloat16* Crow = g_ew1 + (size_t)gm * N + bn + tc;
        *(__nv_bfloat162*)(Crow)     = __floats2bfloat162_rn(acc[i][0], acc[i][1]);
        *(__nv_bfloat162*)(Crow + 2) = __floats2bfloat162_rn(acc[i][2], acc[i][3]);
    }
}

// ---------------- launch ----------------
extern "C" void kernel_launch(void* const* d_in, const int* in_sizes, int n_in,
                              void* d_out, int out_size) {
    const float* x  = (const float*)d_in[0];
    const int* edge = (const int*)d_in[1];
    const float* W1 = (const float*)d_in[2];
    const float* b1 = (const float*)d_in[3];
    const float* W2 = (const float*)d_in[4];
    const float* b2 = (const float*)d_in[5];
    float* out = (float*)d_out;
    const int* nidx = edge;
    const int* hidx = edge + NNZ;

    // prep + CSR build (4 launches)
    k_prep<<<(N_NODES * IN_C / 4 + 255) / 256, 256>>>(x);
    k_count<<<(NNZ + 255) / 256, 256>>>(nidx, hidx);
    k_scan<<<NB_N + NB_H, 512>>>();
    k_fill<<<(NNZ + 255) / 256, 256>>>(nidx, hidx);

    // Layer 1: hedge agg @128 (bf16 gather) -> hedge GEMM (bf16 out) -> fused node-agg + GEMM2
    k_hedge_agg128<<<(N_HEDGES * 32 + 255) / 256, 256>>>();
    {
        dim3 grid(D1 / 64, (N_HEDGES + 63) / 64);
        k_gemm_e1<<<grid, 256>>>(W1);
    }
    k_agg256_gemm2<<<(N_NODES + 31) / 32, 256>>>(b1, W2);

    // Layer 2 tail: bf16 down/up aggregation, fp32 output epilogue
    k_hedge_agg64<<<(N_HEDGES * 32 + 255) / 256, 256>>>();
    k_node_agg64_out<<<(N_NODES * 32 + 255) / 256, 256>>>(b2, out);
}